// round 5
// baseline (speedup 1.0000x reference)
#include <cuda_runtime.h>
#include <cuda_bf16.h>
#include <math.h>
#include <float.h>
#include <stdint.h>

#define BATCH 2
#define SEQ   2048
#define DIM   1024
#define NH    16
#define DH    64
#define WIN   512
#define E3    3072
#define MTOT  (BATCH * SEQ)   // 4096
#define KD    1024

// ---------------- scratch (device globals; no allocation) ------------------
__device__ __nv_bfloat16 g_xh[MTOT * KD],  g_xl[MTOT * KD];   // split x
__device__ __nv_bfloat16 g_wqh[E3 * KD],   g_wql[E3 * KD];    // Wqkv^T split
__device__ __nv_bfloat16 g_woh[DIM * KD],  g_wol[DIM * KD];   // Wout^T split
__device__ __nv_bfloat16 g_qh[MTOT * E3],  g_ql[MTOT * E3];   // split qkv
__device__ __nv_bfloat16 g_ch[MTOT * KD],  g_cl[MTOT * KD];   // split ctx

// ---------------- helpers ---------------------------------------------------
__device__ __forceinline__ uint32_t pack_bf16(float lo, float hi) {
    uint32_t r;
    asm("cvt.rn.bf16x2.f32 %0, %1, %2;" : "=r"(r) : "f"(hi), "f"(lo));
    return r;
}
__device__ __forceinline__ void split_pair(float x, float y, uint32_t& hi, uint32_t& lo) {
    hi = pack_bf16(x, y);
    float xh = __uint_as_float(hi << 16);
    float yh = __uint_as_float(hi & 0xFFFF0000u);
    lo = pack_bf16(x - xh, y - yh);
}
__device__ __forceinline__ void mma_bf16(float* c, const uint32_t* a, const uint32_t* b) {
    asm volatile(
        "mma.sync.aligned.m16n8k16.row.col.f32.bf16.bf16.f32 "
        "{%0,%1,%2,%3}, {%4,%5,%6,%7}, {%8,%9}, {%0,%1,%2,%3};"
        : "+f"(c[0]), "+f"(c[1]), "+f"(c[2]), "+f"(c[3])
        : "r"(a[0]), "r"(a[1]), "r"(a[2]), "r"(a[3]), "r"(b[0]), "r"(b[1]));
}
__device__ __forceinline__ uint32_t smem_u32(const void* p) {
    return (uint32_t)__cvta_generic_to_shared(p);
}
#define CP16(s, g) \
    asm volatile("cp.async.cg.shared.global [%0], [%1], 16;" :: "r"(s), "l"(g))
#define CP_COMMIT() asm volatile("cp.async.commit_group;")
#define CP_WAIT(n)  asm volatile("cp.async.wait_group %0;" :: "n"(n))
#define LDSM4(r, a) \
    asm volatile("ldmatrix.sync.aligned.m8n8.x4.shared.b16 {%0,%1,%2,%3}, [%4];" \
        : "=r"((r)[0]), "=r"((r)[1]), "=r"((r)[2]), "=r"((r)[3]) : "r"(a))
#define LDSM4T(r, a) \
    asm volatile("ldmatrix.sync.aligned.m8n8.x4.trans.shared.b16 {%0,%1,%2,%3}, [%4];" \
        : "=r"((r)[0]), "=r"((r)[1]), "=r"((r)[2]), "=r"((r)[3]) : "r"(a))

// ---------------------------------------------------------------------------
// Prep kernels
// ---------------------------------------------------------------------------
__global__ __launch_bounds__(256) void split_x_kernel(
    const float* __restrict__ x, __nv_bfloat16* __restrict__ xh,
    __nv_bfloat16* __restrict__ xl)
{
    int i = blockIdx.x * 256 + threadIdx.x;
    float4 v = ((const float4*)x)[i];
    uint32_t h0, l0, h1, l1;
    split_pair(v.x, v.y, h0, l0);
    split_pair(v.z, v.w, h1, l1);
    ((uint2*)xh)[i] = make_uint2(h0, h1);
    ((uint2*)xl)[i] = make_uint2(l0, l1);
}

// W[K][N] fp32 -> Wt hi/lo [N][K] bf16
__global__ __launch_bounds__(256) void tsplit_kernel(
    const float* __restrict__ W, __nv_bfloat16* __restrict__ Wth,
    __nv_bfloat16* __restrict__ Wtl, int N, int K)
{
    __shared__ float tile[32][33];
    int tx = threadIdx.x, ty = threadIdx.y;
    int n0 = blockIdx.x * 32, k0 = blockIdx.y * 32;
#pragma unroll
    for (int i = 0; i < 4; i++)
        tile[ty + 8 * i][tx] = W[(long)(k0 + ty + 8 * i) * N + n0 + tx];
    __syncthreads();
#pragma unroll
    for (int i = 0; i < 4; i++) {
        int n = ty + 8 * i;
        float v = tile[tx][n];
        __nv_bfloat16 h = __float2bfloat16(v);
        Wth[(long)(n0 + n) * K + k0 + tx] = h;
        Wtl[(long)(n0 + n) * K + k0 + tx] = __float2bfloat16(v - __bfloat162float(h));
    }
}

// ---------------------------------------------------------------------------
// bf16x3 GEMM on mma.sync. C = Ah*Bh + Ah*Bl + Al*Bh.
// A: [M][K] bf16 K-major (pre-split). B: [N][K] bf16 K-major (pre-split).
// Block tile 128x256, BK=32, 256 thr = 8 warps (2m x 4n of 64x64).
// cp.async double-buffered smem; ldmatrix fragments; pass-reordered mma.
// MODE 0: fp32 C.  MODE 1: split bf16 hi/lo C (cols < qcols scaled by 0.125).
// ---------------------------------------------------------------------------
#define LDT      40                         // bf16 per smem row (32 + 8 pad)
#define A_BYTES  (128 * LDT * 2)            // 10240
#define B_BYTES  (256 * LDT * 2)            // 20480
#define STG      (2 * A_BYTES + 2 * B_BYTES)  // 61440
#define GEMM_SMEM (2 * STG)                 // 122880

template <int MODE>
__global__ __launch_bounds__(256) void gemm_mma(
    const __nv_bfloat16* __restrict__ Ah, const __nv_bfloat16* __restrict__ Al,
    const __nv_bfloat16* __restrict__ Bh, const __nv_bfloat16* __restrict__ Bl,
    float* __restrict__ Cf, __nv_bfloat16* __restrict__ Ch,
    __nv_bfloat16* __restrict__ Cl, int M, int N, int K, int qcols)
{
    extern __shared__ char smem[];
    const uint32_t sb = smem_u32(smem);
    const int tid = threadIdx.x, wid = tid >> 5, lane = tid & 31;
    const int wm = (wid & 1) * 64, wn = (wid >> 1) * 64;
    const long arow0 = (long)blockIdx.y * 128;
    const long brow0 = (long)blockIdx.x * 256;

    float acc[4][8][4] = {};

    // fragment base offsets (within a stage)
    const uint32_t a_off =
        (uint32_t)((wm + (lane & 7) + ((lane & 8) ? 8 : 0)) * (LDT * 2)
                   + ((lane & 16) ? 16 : 0));
    const uint32_t b_off = (uint32_t)(2 * A_BYTES
                   + (wn + (lane & 7) + ((lane & 16) ? 8 : 0)) * (LDT * 2)
                   + ((lane & 8) ? 16 : 0));

    const int nT = K / 32;

    auto issue = [&](int t) {
        const int s = t & 1, k0 = t * 32;
        const uint32_t st = sb + s * STG;
        // A hi/lo: 512 chunks each
#pragma unroll
        for (int i = 0; i < 2; i++) {
            int idx = i * 256 + tid;
            int row = idx >> 2, kc = idx & 3;
            uint32_t so = st + row * (LDT * 2) + kc * 16;
            long go = (arow0 + row) * K + k0 + kc * 8;
            CP16(so, Ah + go);
            CP16(so + A_BYTES, Al + go);
        }
        // B hi/lo: 1024 chunks each
#pragma unroll
        for (int i = 0; i < 4; i++) {
            int idx = i * 256 + tid;
            int row = idx >> 2, kc = idx & 3;
            uint32_t so = st + 2 * A_BYTES + row * (LDT * 2) + kc * 16;
            long go = (brow0 + row) * K + k0 + kc * 8;
            CP16(so, Bh + go);
            CP16(so + B_BYTES, Bl + go);
        }
        CP_COMMIT();
    };

    issue(0);
    for (int t = 0; t < nT; t++) {
        if (t + 1 < nT) { issue(t + 1); CP_WAIT(1); }
        else            { CP_WAIT(0); }
        __syncthreads();

        const uint32_t st = sb + (t & 1) * STG;
#pragma unroll
        for (int ks = 0; ks < 2; ks++) {
            uint32_t ah[4][4], al[4][4], bh[8][2], bl[8][2];
#pragma unroll
            for (int am = 0; am < 4; am++) {
                uint32_t a = st + a_off + am * (16 * LDT * 2) + ks * 32;
                LDSM4(ah[am], a);
                LDSM4(al[am], a + A_BYTES);
            }
#pragma unroll
            for (int g = 0; g < 4; g++) {
                uint32_t a = st + b_off + g * (16 * LDT * 2) + ks * 32;
                uint32_t r[4];
                LDSM4(r, a);
                bh[2*g][0] = r[0]; bh[2*g][1] = r[1];
                bh[2*g+1][0] = r[2]; bh[2*g+1][1] = r[3];
                LDSM4(r, a + B_BYTES);
                bl[2*g][0] = r[0]; bl[2*g][1] = r[1];
                bl[2*g+1][0] = r[2]; bl[2*g+1][1] = r[3];
            }
#pragma unroll
            for (int am = 0; am < 4; am++)
#pragma unroll
                for (int bn = 0; bn < 8; bn++)
                    mma_bf16(acc[am][bn], al[am], bh[bn]);
#pragma unroll
            for (int am = 0; am < 4; am++)
#pragma unroll
                for (int bn = 0; bn < 8; bn++)
                    mma_bf16(acc[am][bn], ah[am], bl[bn]);
#pragma unroll
            for (int am = 0; am < 4; am++)
#pragma unroll
                for (int bn = 0; bn < 8; bn++)
                    mma_bf16(acc[am][bn], ah[am], bh[bn]);
        }
        __syncthreads();
    }

    // epilogue
#pragma unroll
    for (int am = 0; am < 4; am++)
#pragma unroll
        for (int bn = 0; bn < 8; bn++) {
            int row = blockIdx.y * 128 + wm + am * 16 + (lane >> 2);
            int col = blockIdx.x * 256 + wn + bn * 8 + 2 * (lane & 3);
            if (MODE == 0) {
                *(float2*)(Cf + (long)row * N + col) =
                    make_float2(acc[am][bn][0], acc[am][bn][1]);
                *(float2*)(Cf + (long)(row + 8) * N + col) =
                    make_float2(acc[am][bn][2], acc[am][bn][3]);
            } else {
                float scl = (col < qcols) ? 0.125f : 1.0f;
                uint32_t hh, ll;
                split_pair(acc[am][bn][0] * scl, acc[am][bn][1] * scl, hh, ll);
                *(uint32_t*)(Ch + (long)row * N + col) = hh;
                *(uint32_t*)(Cl + (long)row * N + col) = ll;
                split_pair(acc[am][bn][2] * scl, acc[am][bn][3] * scl, hh, ll);
                *(uint32_t*)(Ch + (long)(row + 8) * N + col) = hh;
                *(uint32_t*)(Cl + (long)(row + 8) * N + col) = ll;
            }
        }
}

// ---------------------------------------------------------------------------
// Sliding-window flash attention, bf16 hi/lo 3-pass on mma.sync.
// Inputs pre-split (Q pre-scaled). 128 q-rows/block, 4 warps, key tile 64.
// ---------------------------------------------------------------------------
#define KVP 72   // bf16 per smem row (64 + 8 pad); 144B rows, 16B aligned

__global__ __launch_bounds__(128) void attn_mma(
    const __nv_bfloat16* __restrict__ qh, const __nv_bfloat16* __restrict__ ql,
    __nv_bfloat16* __restrict__ ctxh, __nv_bfloat16* __restrict__ ctxl)
{
    __shared__ __nv_bfloat16 Kh[64 * KVP], Kl[64 * KVP];
    __shared__ __nv_bfloat16 Vh[64 * KVP], Vl[64 * KVP];

    const int tid  = threadIdx.x;
    const int wid  = tid >> 5;
    const int lane = tid & 31;
    const int gid  = lane >> 2;
    const int tig  = lane & 3;
    const int i0   = blockIdx.x * 128;
    const int h    = blockIdx.y;
    const int b    = blockIdx.z;

    const long rowb = (long)b * SEQ;
    const int qcol = h * DH;           // q columns
    const int kcol = DIM + h * DH;     // k columns
    const int vcol = 2 * DIM + h * DH; // v columns

    // Q fragments (already scaled + split by GEMM1 epilogue)
    uint32_t qfh[2][4][4], qfl[2][4][4];
#pragma unroll
    for (int am = 0; am < 2; am++) {
        long r = rowb + i0 + wid * 32 + am * 16 + gid;
#pragma unroll
        for (int s = 0; s < 4; s++) {
            int c = qcol + s * 16 + 2 * tig;
            qfh[am][s][0] = *(const uint32_t*)(qh + r * E3 + c);
            qfh[am][s][1] = *(const uint32_t*)(qh + (r + 8) * E3 + c);
            qfh[am][s][2] = *(const uint32_t*)(qh + r * E3 + c + 8);
            qfh[am][s][3] = *(const uint32_t*)(qh + (r + 8) * E3 + c + 8);
            qfl[am][s][0] = *(const uint32_t*)(ql + r * E3 + c);
            qfl[am][s][1] = *(const uint32_t*)(ql + (r + 8) * E3 + c);
            qfl[am][s][2] = *(const uint32_t*)(ql + r * E3 + c + 8);
            qfl[am][s][3] = *(const uint32_t*)(ql + (r + 8) * E3 + c + 8);
        }
    }

    // ldmatrix base offsets
    const uint32_t kh_b = smem_u32(Kh), kl_b = smem_u32(Kl);
    const uint32_t vh_b = smem_u32(Vh), vl_b = smem_u32(Vl);
    // K (non-trans): row = key = g*16 + (lane&7) + ((lane&16)?8:0); kblk dh + ((lane&8)?8:0)
    const uint32_t koff = (uint32_t)(((lane & 7) + ((lane & 16) ? 8 : 0)) * (KVP * 2)
                                     + ((lane & 8) ? 16 : 0));
    // V (trans): row = key = kk*16 + (lane&7) + ((lane&8)?8:0); ncol dh + ((lane&16)?8:0)
    const uint32_t voff = (uint32_t)(((lane & 7) + ((lane & 8) ? 8 : 0)) * (KVP * 2)
                                     + ((lane & 16) ? 16 : 0));

    float mrow[2][2], lrow[2][2], o[2][8][4] = {};
#pragma unroll
    for (int am = 0; am < 2; am++) {
        mrow[am][0] = -FLT_MAX; mrow[am][1] = -FLT_MAX;
        lrow[am][0] = 0.f;      lrow[am][1] = 0.f;
    }

    int t0 = (i0 - WIN + 1) >> 6; if (t0 < 0) t0 = 0;
    const int t1 = (i0 + 127) >> 6;

    for (int t = t0; t <= t1; t++) {
        const int kt0 = t << 6;
        __syncthreads();   // previous tile's readers done

        // cp.async K/V hi+lo tiles (64 x 64 bf16 each)
#pragma unroll
        for (int i = 0; i < 4; i++) {
            int idx = i * 128 + tid;
            int row = idx >> 3, ch = idx & 7;
            long gro = (rowb + kt0 + row) * E3;
            uint32_t so = row * (KVP * 2) + ch * 16;
            CP16(kh_b + so, qh + gro + kcol + ch * 8);
            CP16(kl_b + so, ql + gro + kcol + ch * 8);
            CP16(vh_b + so, qh + gro + vcol + ch * 8);
            CP16(vl_b + so, ql + gro + vcol + ch * 8);
        }
        CP_COMMIT();
        CP_WAIT(0);
        __syncthreads();

        // ---- S = Q K^T
        float s[2][8][4] = {};
#pragma unroll
        for (int ks = 0; ks < 4; ks++) {
            uint32_t kh[8][2], kl[8][2];
#pragma unroll
            for (int g = 0; g < 4; g++) {
                uint32_t a = koff + g * (16 * KVP * 2) + ks * 32;
                uint32_t r[4];
                LDSM4(r, kh_b + a);
                kh[2*g][0] = r[0]; kh[2*g][1] = r[1];
                kh[2*g+1][0] = r[2]; kh[2*g+1][1] = r[3];
                LDSM4(r, kl_b + a);
                kl[2*g][0] = r[0]; kl[2*g][1] = r[1];
                kl[2*g+1][0] = r[2]; kl[2*g+1][1] = r[3];
            }
#pragma unroll
            for (int bn = 0; bn < 8; bn++)
#pragma unroll
                for (int am = 0; am < 2; am++)
                    mma_bf16(s[am][bn], qfl[am][ks], kh[bn]);
#pragma unroll
            for (int bn = 0; bn < 8; bn++)
#pragma unroll
                for (int am = 0; am < 2; am++)
                    mma_bf16(s[am][bn], qfh[am][ks], kl[bn]);
#pragma unroll
            for (int bn = 0; bn < 8; bn++)
#pragma unroll
                for (int am = 0; am < 2; am++)
                    mma_bf16(s[am][bn], qfh[am][ks], kh[bn]);
        }

        // ---- mask + online softmax
#pragma unroll
        for (int am = 0; am < 2; am++) {
            int qi0 = i0 + wid * 32 + am * 16 + gid;
            int qi1 = qi0 + 8;
#pragma unroll
            for (int bn = 0; bn < 8; bn++) {
                int c0 = kt0 + bn * 8 + 2 * tig, c1 = c0 + 1;
                if (c0 > qi0 || c0 < qi0 - (WIN - 1)) s[am][bn][0] = -FLT_MAX;
                if (c1 > qi0 || c1 < qi0 - (WIN - 1)) s[am][bn][1] = -FLT_MAX;
                if (c0 > qi1 || c0 < qi1 - (WIN - 1)) s[am][bn][2] = -FLT_MAX;
                if (c1 > qi1 || c1 < qi1 - (WIN - 1)) s[am][bn][3] = -FLT_MAX;
            }
            float mx0 = -FLT_MAX, mx1 = -FLT_MAX;
#pragma unroll
            for (int bn = 0; bn < 8; bn++) {
                mx0 = fmaxf(mx0, fmaxf(s[am][bn][0], s[am][bn][1]));
                mx1 = fmaxf(mx1, fmaxf(s[am][bn][2], s[am][bn][3]));
            }
            mx0 = fmaxf(mx0, __shfl_xor_sync(0xffffffffu, mx0, 1));
            mx0 = fmaxf(mx0, __shfl_xor_sync(0xffffffffu, mx0, 2));
            mx1 = fmaxf(mx1, __shfl_xor_sync(0xffffffffu, mx1, 1));
            mx1 = fmaxf(mx1, __shfl_xor_sync(0xffffffffu, mx1, 2));
            float mn0 = fmaxf(mrow[am][0], mx0);
            float mn1 = fmaxf(mrow[am][1], mx1);
            float a0 = __expf(mrow[am][0] - mn0);
            float a1 = __expf(mrow[am][1] - mn1);
            mrow[am][0] = mn0; mrow[am][1] = mn1;
            float rs0 = 0.f, rs1 = 0.f;
#pragma unroll
            for (int bn = 0; bn < 8; bn++) {
                s[am][bn][0] = __expf(s[am][bn][0] - mn0);
                s[am][bn][1] = __expf(s[am][bn][1] - mn0);
                s[am][bn][2] = __expf(s[am][bn][2] - mn1);
                s[am][bn][3] = __expf(s[am][bn][3] - mn1);
                rs0 += s[am][bn][0] + s[am][bn][1];
                rs1 += s[am][bn][2] + s[am][bn][3];
            }
            rs0 += __shfl_xor_sync(0xffffffffu, rs0, 1);
            rs0 += __shfl_xor_sync(0xffffffffu, rs0, 2);
            rs1 += __shfl_xor_sync(0xffffffffu, rs1, 1);
            rs1 += __shfl_xor_sync(0xffffffffu, rs1, 2);
            lrow[am][0] = lrow[am][0] * a0 + rs0;
            lrow[am][1] = lrow[am][1] * a1 + rs1;
#pragma unroll
            for (int bn = 0; bn < 8; bn++) {
                o[am][bn][0] *= a0; o[am][bn][1] *= a0;
                o[am][bn][2] *= a1; o[am][bn][3] *= a1;
            }
        }

        // ---- P fragments (hi/lo) straight from S accumulators
        uint32_t pf[2][4][4], pg[2][4][4];
#pragma unroll
        for (int am = 0; am < 2; am++)
#pragma unroll
            for (int kk = 0; kk < 4; kk++) {
                split_pair(s[am][2*kk][0],   s[am][2*kk][1],   pf[am][kk][0], pg[am][kk][0]);
                split_pair(s[am][2*kk][2],   s[am][2*kk][3],   pf[am][kk][1], pg[am][kk][1]);
                split_pair(s[am][2*kk+1][0], s[am][2*kk+1][1], pf[am][kk][2], pg[am][kk][2]);
                split_pair(s[am][2*kk+1][2], s[am][2*kk+1][3], pf[am][kk][3], pg[am][kk][3]);
            }

        // ---- O += P V
#pragma unroll
        for (int kk = 0; kk < 4; kk++) {
            uint32_t vh[8][2], vl[8][2];
#pragma unroll
            for (int g = 0; g < 4; g++) {
                uint32_t a = voff + kk * (16 * KVP * 2) + g * 32;
                uint32_t r[4];
                LDSM4T(r, vh_b + a);
                vh[2*g][0] = r[0]; vh[2*g][1] = r[1];
                vh[2*g+1][0] = r[2]; vh[2*g+1][1] = r[3];
                LDSM4T(r, vl_b + a);
                vl[2*g][0] = r[0]; vl[2*g][1] = r[1];
                vl[2*g+1][0] = r[2]; vl[2*g+1][1] = r[3];
            }
#pragma unroll
            for (int bn = 0; bn < 8; bn++)
#pragma unroll
                for (int am = 0; am < 2; am++)
                    mma_bf16(o[am][bn], pg[am][kk], vh[bn]);
#pragma unroll
            for (int bn = 0; bn < 8; bn++)
#pragma unroll
                for (int am = 0; am < 2; am++)
                    mma_bf16(o[am][bn], pf[am][kk], vl[bn]);
#pragma unroll
            for (int bn = 0; bn < 8; bn++)
#pragma unroll
                for (int am = 0; am < 2; am++)
                    mma_bf16(o[am][bn], pf[am][kk], vh[bn]);
        }
    }

    // ---- epilogue: normalize, split, store ctx hi/lo
#pragma unroll
    for (int am = 0; am < 2; am++) {
        float inv0 = 1.f / lrow[am][0];
        float inv1 = 1.f / lrow[am][1];
        long r0 = rowb + i0 + wid * 32 + am * 16 + gid;
#pragma unroll
        for (int bn = 0; bn < 8; bn++) {
            int col = h * DH + bn * 8 + 2 * tig;
            uint32_t hh, ll;
            split_pair(o[am][bn][0] * inv0, o[am][bn][1] * inv0, hh, ll);
            *(uint32_t*)(ctxh + r0 * DIM + col) = hh;
            *(uint32_t*)(ctxl + r0 * DIM + col) = ll;
            split_pair(o[am][bn][2] * inv1, o[am][bn][3] * inv1, hh, ll);
            *(uint32_t*)(ctxh + (r0 + 8) * DIM + col) = hh;
            *(uint32_t*)(ctxl + (r0 + 8) * DIM + col) = ll;
        }
    }
}

// ---------------------------------------------------------------------------
extern "C" void kernel_launch(void* const* d_in, const int* in_sizes, int n_in,
                              void* d_out, int out_size)
{
    (void)in_sizes; (void)n_in; (void)out_size;
    const float* x    = (const float*)d_in[0];
    const float* Wqkv = (const float*)d_in[1];
    const float* Wout = (const float*)d_in[2];
    float* out = (float*)d_out;

    __nv_bfloat16 *xh, *xl, *wqh, *wql, *woh, *wol, *qh, *ql, *ch, *cl;
    cudaGetSymbolAddress((void**)&xh,  g_xh);
    cudaGetSymbolAddress((void**)&xl,  g_xl);
    cudaGetSymbolAddress((void**)&wqh, g_wqh);
    cudaGetSymbolAddress((void**)&wql, g_wql);
    cudaGetSymbolAddress((void**)&woh, g_woh);
    cudaGetSymbolAddress((void**)&wol, g_wol);
    cudaGetSymbolAddress((void**)&qh,  g_qh);
    cudaGetSymbolAddress((void**)&ql,  g_ql);
    cudaGetSymbolAddress((void**)&ch,  g_ch);
    cudaGetSymbolAddress((void**)&cl,  g_cl);

    cudaFuncSetAttribute(gemm_mma<0>,
                         cudaFuncAttributeMaxDynamicSharedMemorySize, GEMM_SMEM);
    cudaFuncSetAttribute(gemm_mma<1>,
                         cudaFuncAttributeMaxDynamicSharedMemorySize, GEMM_SMEM);

    // prep
    split_x_kernel<<<(MTOT * KD) / 1024, 256>>>(x, xh, xl);
    tsplit_kernel<<<dim3(E3 / 32, KD / 32), dim3(32, 8)>>>(Wqkv, wqh, wql, E3, KD);
    tsplit_kernel<<<dim3(DIM / 32, KD / 32), dim3(32, 8)>>>(Wout, woh, wol, DIM, KD);

    // 1) QKV projection -> split qkv (Q columns pre-scaled)
    gemm_mma<1><<<dim3(E3 / 256, MTOT / 128), 256, GEMM_SMEM>>>(
        xh, xl, wqh, wql, nullptr, qh, ql, MTOT, E3, KD, DIM);

    // 2) sliding-window attention -> split ctx
    attn_mma<<<dim3(SEQ / 128, NH, BATCH), 128>>>(qh, ql, ch, cl);

    // 3) output projection -> fp32 out
    gemm_mma<0><<<dim3(DIM / 256, MTOT / 128), 256, GEMM_SMEM>>>(
        ch, cl, woh, wol, out, nullptr, nullptr, MTOT, DIM, KD, 0);
}

// round 6
// speedup vs baseline: 1.0001x; 1.0001x over previous
#include <cuda_runtime.h>
#include <cuda_bf16.h>
#include <math.h>
#include <float.h>
#include <stdint.h>

#define BATCH 2
#define SEQ   2048
#define DIM   1024
#define NH    16
#define DH    64
#define WIN   512
#define E3    3072
#define MTOT  (BATCH * SEQ)   // 4096
#define KD    1024

// ---------------- scratch (device globals; no allocation) ------------------
__device__ __nv_bfloat16 g_xh[MTOT * KD],  g_xl[MTOT * KD];   // split x
__device__ __nv_bfloat16 g_wqh[E3 * KD],   g_wql[E3 * KD];    // Wqkv^T split
__device__ __nv_bfloat16 g_woh[DIM * KD],  g_wol[DIM * KD];   // Wout^T split
__device__ __nv_bfloat16 g_qh[MTOT * E3],  g_ql[MTOT * E3];   // split qkv
__device__ __nv_bfloat16 g_ch[MTOT * KD],  g_cl[MTOT * KD];   // split ctx

// ---------------- helpers ---------------------------------------------------
__device__ __forceinline__ uint32_t pack_bf16(float lo, float hi) {
    uint32_t r;
    asm("cvt.rn.bf16x2.f32 %0, %1, %2;" : "=r"(r) : "f"(hi), "f"(lo));
    return r;
}
__device__ __forceinline__ void split_pair(float x, float y, uint32_t& hi, uint32_t& lo) {
    hi = pack_bf16(x, y);
    float xh = __uint_as_float(hi << 16);
    float yh = __uint_as_float(hi & 0xFFFF0000u);
    lo = pack_bf16(x - xh, y - yh);
}
__device__ __forceinline__ void mma_bf16(float* c, const uint32_t* a, const uint32_t* b) {
    asm volatile(
        "mma.sync.aligned.m16n8k16.row.col.f32.bf16.bf16.f32 "
        "{%0,%1,%2,%3}, {%4,%5,%6,%7}, {%8,%9}, {%0,%1,%2,%3};"
        : "+f"(c[0]), "+f"(c[1]), "+f"(c[2]), "+f"(c[3])
        : "r"(a[0]), "r"(a[1]), "r"(a[2]), "r"(a[3]), "r"(b[0]), "r"(b[1]));
}
__device__ __forceinline__ uint32_t smem_u32(const void* p) {
    return (uint32_t)__cvta_generic_to_shared(p);
}
#define CP16(s, g) \
    asm volatile("cp.async.cg.shared.global [%0], [%1], 16;" :: "r"(s), "l"(g))
#define CP_COMMIT() asm volatile("cp.async.commit_group;")
#define CP_WAIT(n)  asm volatile("cp.async.wait_group %0;" :: "n"(n))
#define LDSM4(r, a) \
    asm volatile("ldmatrix.sync.aligned.m8n8.x4.shared.b16 {%0,%1,%2,%3}, [%4];" \
        : "=r"((r)[0]), "=r"((r)[1]), "=r"((r)[2]), "=r"((r)[3]) : "r"(a))
#define LDSM4T(r, a) \
    asm volatile("ldmatrix.sync.aligned.m8n8.x4.trans.shared.b16 {%0,%1,%2,%3}, [%4];" \
        : "=r"((r)[0]), "=r"((r)[1]), "=r"((r)[2]), "=r"((r)[3]) : "r"(a))

// ---------------------------------------------------------------------------
// Prep kernels
// ---------------------------------------------------------------------------
__global__ __launch_bounds__(256) void split_x_kernel(
    const float* __restrict__ x, __nv_bfloat16* __restrict__ xh,
    __nv_bfloat16* __restrict__ xl)
{
    int i = blockIdx.x * 256 + threadIdx.x;
    float4 v = ((const float4*)x)[i];
    uint32_t h0, l0, h1, l1;
    split_pair(v.x, v.y, h0, l0);
    split_pair(v.z, v.w, h1, l1);
    ((uint2*)xh)[i] = make_uint2(h0, h1);
    ((uint2*)xl)[i] = make_uint2(l0, l1);
}

// W[K][N] fp32 -> Wt hi/lo [N][K] bf16
__global__ __launch_bounds__(256) void tsplit_kernel(
    const float* __restrict__ W, __nv_bfloat16* __restrict__ Wth,
    __nv_bfloat16* __restrict__ Wtl, int N, int K)
{
    __shared__ float tile[32][33];
    int tx = threadIdx.x, ty = threadIdx.y;
    int n0 = blockIdx.x * 32, k0 = blockIdx.y * 32;
#pragma unroll
    for (int i = 0; i < 4; i++)
        tile[ty + 8 * i][tx] = W[(long)(k0 + ty + 8 * i) * N + n0 + tx];
    __syncthreads();
#pragma unroll
    for (int i = 0; i < 4; i++) {
        int n = ty + 8 * i;
        float v = tile[tx][n];
        __nv_bfloat16 h = __float2bfloat16(v);
        Wth[(long)(n0 + n) * K + k0 + tx] = h;
        Wtl[(long)(n0 + n) * K + k0 + tx] = __float2bfloat16(v - __bfloat162float(h));
    }
}

// ---------------------------------------------------------------------------
// bf16x3 GEMM on mma.sync. C = Ah*Bh + Ah*Bl + Al*Bh.
// A: [M][K] bf16 K-major (pre-split). B: [N][K] bf16 K-major (pre-split).
// Block tile 128x256, BK=32, 256 thr = 8 warps (2m x 4n of 64x64).
// cp.async double-buffered smem; ldmatrix fragments; pass-reordered mma.
// MODE 0: fp32 C.  MODE 1: split bf16 hi/lo C (cols < qcols scaled by 0.125).
// ---------------------------------------------------------------------------
#define LDT      40                         // bf16 per smem row (32 + 8 pad)
#define A_BYTES  (128 * LDT * 2)            // 10240
#define B_BYTES  (256 * LDT * 2)            // 20480
#define STG      (2 * A_BYTES + 2 * B_BYTES)  // 61440
#define GEMM_SMEM (2 * STG)                 // 122880

template <int MODE>
__global__ __launch_bounds__(256) void gemm_mma(
    const __nv_bfloat16* __restrict__ Ah, const __nv_bfloat16* __restrict__ Al,
    const __nv_bfloat16* __restrict__ Bh, const __nv_bfloat16* __restrict__ Bl,
    float* __restrict__ Cf, __nv_bfloat16* __restrict__ Ch,
    __nv_bfloat16* __restrict__ Cl, int M, int N, int K, int qcols)
{
    extern __shared__ char smem[];
    const uint32_t sb = smem_u32(smem);
    const int tid = threadIdx.x, wid = tid >> 5, lane = tid & 31;
    const int wm = (wid & 1) * 64, wn = (wid >> 1) * 64;
    const long arow0 = (long)blockIdx.y * 128;
    const long brow0 = (long)blockIdx.x * 256;

    float acc[4][8][4] = {};

    // fragment base offsets (within a stage)
    const uint32_t a_off =
        (uint32_t)((wm + (lane & 7) + ((lane & 8) ? 8 : 0)) * (LDT * 2)
                   + ((lane & 16) ? 16 : 0));
    const uint32_t b_off = (uint32_t)(2 * A_BYTES
                   + (wn + (lane & 7) + ((lane & 16) ? 8 : 0)) * (LDT * 2)
                   + ((lane & 8) ? 16 : 0));

    const int nT = K / 32;

    auto issue = [&](int t) {
        const int s = t & 1, k0 = t * 32;
        const uint32_t st = sb + s * STG;
        // A hi/lo: 512 chunks each
#pragma unroll
        for (int i = 0; i < 2; i++) {
            int idx = i * 256 + tid;
            int row = idx >> 2, kc = idx & 3;
            uint32_t so = st + row * (LDT * 2) + kc * 16;
            long go = (arow0 + row) * K + k0 + kc * 8;
            CP16(so, Ah + go);
            CP16(so + A_BYTES, Al + go);
        }
        // B hi/lo: 1024 chunks each
#pragma unroll
        for (int i = 0; i < 4; i++) {
            int idx = i * 256 + tid;
            int row = idx >> 2, kc = idx & 3;
            uint32_t so = st + 2 * A_BYTES + row * (LDT * 2) + kc * 16;
            long go = (brow0 + row) * K + k0 + kc * 8;
            CP16(so, Bh + go);
            CP16(so + B_BYTES, Bl + go);
        }
        CP_COMMIT();
    };

    issue(0);
    for (int t = 0; t < nT; t++) {
        if (t + 1 < nT) { issue(t + 1); CP_WAIT(1); }
        else            { CP_WAIT(0); }
        __syncthreads();

        const uint32_t st = sb + (t & 1) * STG;
#pragma unroll
        for (int ks = 0; ks < 2; ks++) {
            uint32_t ah[4][4], al[4][4], bh[8][2], bl[8][2];
#pragma unroll
            for (int am = 0; am < 4; am++) {
                uint32_t a = st + a_off + am * (16 * LDT * 2) + ks * 32;
                LDSM4(ah[am], a);
                LDSM4(al[am], a + A_BYTES);
            }
#pragma unroll
            for (int g = 0; g < 4; g++) {
                uint32_t a = st + b_off + g * (16 * LDT * 2) + ks * 32;
                uint32_t r[4];
                LDSM4(r, a);
                bh[2*g][0] = r[0]; bh[2*g][1] = r[1];
                bh[2*g+1][0] = r[2]; bh[2*g+1][1] = r[3];
                LDSM4(r, a + B_BYTES);
                bl[2*g][0] = r[0]; bl[2*g][1] = r[1];
                bl[2*g+1][0] = r[2]; bl[2*g+1][1] = r[3];
            }
#pragma unroll
            for (int am = 0; am < 4; am++)
#pragma unroll
                for (int bn = 0; bn < 8; bn++)
                    mma_bf16(acc[am][bn], al[am], bh[bn]);
#pragma unroll
            for (int am = 0; am < 4; am++)
#pragma unroll
                for (int bn = 0; bn < 8; bn++)
                    mma_bf16(acc[am][bn], ah[am], bl[bn]);
#pragma unroll
            for (int am = 0; am < 4; am++)
#pragma unroll
                for (int bn = 0; bn < 8; bn++)
                    mma_bf16(acc[am][bn], ah[am], bh[bn]);
        }
        __syncthreads();
    }

    // epilogue
#pragma unroll
    for (int am = 0; am < 4; am++)
#pragma unroll
        for (int bn = 0; bn < 8; bn++) {
            int row = blockIdx.y * 128 + wm + am * 16 + (lane >> 2);
            int col = blockIdx.x * 256 + wn + bn * 8 + 2 * (lane & 3);
            if (MODE == 0) {
                *(float2*)(Cf + (long)row * N + col) =
                    make_float2(acc[am][bn][0], acc[am][bn][1]);
                *(float2*)(Cf + (long)(row + 8) * N + col) =
                    make_float2(acc[am][bn][2], acc[am][bn][3]);
            } else {
                float scl = (col < qcols) ? 0.125f : 1.0f;
                uint32_t hh, ll;
                split_pair(acc[am][bn][0] * scl, acc[am][bn][1] * scl, hh, ll);
                *(uint32_t*)(Ch + (long)row * N + col) = hh;
                *(uint32_t*)(Cl + (long)row * N + col) = ll;
                split_pair(acc[am][bn][2] * scl, acc[am][bn][3] * scl, hh, ll);
                *(uint32_t*)(Ch + (long)(row + 8) * N + col) = hh;
                *(uint32_t*)(Cl + (long)(row + 8) * N + col) = ll;
            }
        }
}

// ---------------------------------------------------------------------------
// Sliding-window flash attention, bf16 hi/lo 3-pass on mma.sync.
// Inputs pre-split (Q pre-scaled). 128 q-rows/block, 4 warps, key tile 64.
// ---------------------------------------------------------------------------
#define KVP 72   // bf16 per smem row (64 + 8 pad); 144B rows, 16B aligned

__global__ __launch_bounds__(128) void attn_mma(
    const __nv_bfloat16* __restrict__ qh, const __nv_bfloat16* __restrict__ ql,
    __nv_bfloat16* __restrict__ ctxh, __nv_bfloat16* __restrict__ ctxl)
{
    __shared__ __nv_bfloat16 Kh[64 * KVP], Kl[64 * KVP];
    __shared__ __nv_bfloat16 Vh[64 * KVP], Vl[64 * KVP];

    const int tid  = threadIdx.x;
    const int wid  = tid >> 5;
    const int lane = tid & 31;
    const int gid  = lane >> 2;
    const int tig  = lane & 3;
    const int i0   = blockIdx.x * 128;
    const int h    = blockIdx.y;
    const int b    = blockIdx.z;

    const long rowb = (long)b * SEQ;
    const int qcol = h * DH;           // q columns
    const int kcol = DIM + h * DH;     // k columns
    const int vcol = 2 * DIM + h * DH; // v columns

    // Q fragments (already scaled + split by GEMM1 epilogue)
    uint32_t qfh[2][4][4], qfl[2][4][4];
#pragma unroll
    for (int am = 0; am < 2; am++) {
        long r = rowb + i0 + wid * 32 + am * 16 + gid;
#pragma unroll
        for (int s = 0; s < 4; s++) {
            int c = qcol + s * 16 + 2 * tig;
            qfh[am][s][0] = *(const uint32_t*)(qh + r * E3 + c);
            qfh[am][s][1] = *(const uint32_t*)(qh + (r + 8) * E3 + c);
            qfh[am][s][2] = *(const uint32_t*)(qh + r * E3 + c + 8);
            qfh[am][s][3] = *(const uint32_t*)(qh + (r + 8) * E3 + c + 8);
            qfl[am][s][0] = *(const uint32_t*)(ql + r * E3 + c);
            qfl[am][s][1] = *(const uint32_t*)(ql + (r + 8) * E3 + c);
            qfl[am][s][2] = *(const uint32_t*)(ql + r * E3 + c + 8);
            qfl[am][s][3] = *(const uint32_t*)(ql + (r + 8) * E3 + c + 8);
        }
    }

    // ldmatrix base offsets
    const uint32_t kh_b = smem_u32(Kh), kl_b = smem_u32(Kl);
    const uint32_t vh_b = smem_u32(Vh), vl_b = smem_u32(Vl);
    // K (non-trans): row = key = g*16 + (lane&7) + ((lane&16)?8:0); kblk dh + ((lane&8)?8:0)
    const uint32_t koff = (uint32_t)(((lane & 7) + ((lane & 16) ? 8 : 0)) * (KVP * 2)
                                     + ((lane & 8) ? 16 : 0));
    // V (trans): row = key = kk*16 + (lane&7) + ((lane&8)?8:0); ncol dh + ((lane&16)?8:0)
    const uint32_t voff = (uint32_t)(((lane & 7) + ((lane & 8) ? 8 : 0)) * (KVP * 2)
                                     + ((lane & 16) ? 16 : 0));

    float mrow[2][2], lrow[2][2], o[2][8][4] = {};
#pragma unroll
    for (int am = 0; am < 2; am++) {
        mrow[am][0] = -FLT_MAX; mrow[am][1] = -FLT_MAX;
        lrow[am][0] = 0.f;      lrow[am][1] = 0.f;
    }

    int t0 = (i0 - WIN + 1) >> 6; if (t0 < 0) t0 = 0;
    const int t1 = (i0 + 127) >> 6;

    for (int t = t0; t <= t1; t++) {
        const int kt0 = t << 6;
        __syncthreads();   // previous tile's readers done

        // cp.async K/V hi+lo tiles (64 x 64 bf16 each)
#pragma unroll
        for (int i = 0; i < 4; i++) {
            int idx = i * 128 + tid;
            int row = idx >> 3, ch = idx & 7;
            long gro = (rowb + kt0 + row) * E3;
            uint32_t so = row * (KVP * 2) + ch * 16;
            CP16(kh_b + so, qh + gro + kcol + ch * 8);
            CP16(kl_b + so, ql + gro + kcol + ch * 8);
            CP16(vh_b + so, qh + gro + vcol + ch * 8);
            CP16(vl_b + so, ql + gro + vcol + ch * 8);
        }
        CP_COMMIT();
        CP_WAIT(0);
        __syncthreads();

        // ---- S = Q K^T
        float s[2][8][4] = {};
#pragma unroll
        for (int ks = 0; ks < 4; ks++) {
            uint32_t kh[8][2], kl[8][2];
#pragma unroll
            for (int g = 0; g < 4; g++) {
                uint32_t a = koff + g * (16 * KVP * 2) + ks * 32;
                uint32_t r[4];
                LDSM4(r, kh_b + a);
                kh[2*g][0] = r[0]; kh[2*g][1] = r[1];
                kh[2*g+1][0] = r[2]; kh[2*g+1][1] = r[3];
                LDSM4(r, kl_b + a);
                kl[2*g][0] = r[0]; kl[2*g][1] = r[1];
                kl[2*g+1][0] = r[2]; kl[2*g+1][1] = r[3];
            }
#pragma unroll
            for (int bn = 0; bn < 8; bn++)
#pragma unroll
                for (int am = 0; am < 2; am++)
                    mma_bf16(s[am][bn], qfl[am][ks], kh[bn]);
#pragma unroll
            for (int bn = 0; bn < 8; bn++)
#pragma unroll
                for (int am = 0; am < 2; am++)
                    mma_bf16(s[am][bn], qfh[am][ks], kl[bn]);
#pragma unroll
            for (int bn = 0; bn < 8; bn++)
#pragma unroll
                for (int am = 0; am < 2; am++)
                    mma_bf16(s[am][bn], qfh[am][ks], kh[bn]);
        }

        // ---- mask + online softmax
#pragma unroll
        for (int am = 0; am < 2; am++) {
            int qi0 = i0 + wid * 32 + am * 16 + gid;
            int qi1 = qi0 + 8;
#pragma unroll
            for (int bn = 0; bn < 8; bn++) {
                int c0 = kt0 + bn * 8 + 2 * tig, c1 = c0 + 1;
                if (c0 > qi0 || c0 < qi0 - (WIN - 1)) s[am][bn][0] = -FLT_MAX;
                if (c1 > qi0 || c1 < qi0 - (WIN - 1)) s[am][bn][1] = -FLT_MAX;
                if (c0 > qi1 || c0 < qi1 - (WIN - 1)) s[am][bn][2] = -FLT_MAX;
                if (c1 > qi1 || c1 < qi1 - (WIN - 1)) s[am][bn][3] = -FLT_MAX;
            }
            float mx0 = -FLT_MAX, mx1 = -FLT_MAX;
#pragma unroll
            for (int bn = 0; bn < 8; bn++) {
                mx0 = fmaxf(mx0, fmaxf(s[am][bn][0], s[am][bn][1]));
                mx1 = fmaxf(mx1, fmaxf(s[am][bn][2], s[am][bn][3]));
            }
            mx0 = fmaxf(mx0, __shfl_xor_sync(0xffffffffu, mx0, 1));
            mx0 = fmaxf(mx0, __shfl_xor_sync(0xffffffffu, mx0, 2));
            mx1 = fmaxf(mx1, __shfl_xor_sync(0xffffffffu, mx1, 1));
            mx1 = fmaxf(mx1, __shfl_xor_sync(0xffffffffu, mx1, 2));
            float mn0 = fmaxf(mrow[am][0], mx0);
            float mn1 = fmaxf(mrow[am][1], mx1);
            float a0 = __expf(mrow[am][0] - mn0);
            float a1 = __expf(mrow[am][1] - mn1);
            mrow[am][0] = mn0; mrow[am][1] = mn1;
            float rs0 = 0.f, rs1 = 0.f;
#pragma unroll
            for (int bn = 0; bn < 8; bn++) {
                s[am][bn][0] = __expf(s[am][bn][0] - mn0);
                s[am][bn][1] = __expf(s[am][bn][1] - mn0);
                s[am][bn][2] = __expf(s[am][bn][2] - mn1);
                s[am][bn][3] = __expf(s[am][bn][3] - mn1);
                rs0 += s[am][bn][0] + s[am][bn][1];
                rs1 += s[am][bn][2] + s[am][bn][3];
            }
            rs0 += __shfl_xor_sync(0xffffffffu, rs0, 1);
            rs0 += __shfl_xor_sync(0xffffffffu, rs0, 2);
            rs1 += __shfl_xor_sync(0xffffffffu, rs1, 1);
            rs1 += __shfl_xor_sync(0xffffffffu, rs1, 2);
            lrow[am][0] = lrow[am][0] * a0 + rs0;
            lrow[am][1] = lrow[am][1] * a1 + rs1;
#pragma unroll
            for (int bn = 0; bn < 8; bn++) {
                o[am][bn][0] *= a0; o[am][bn][1] *= a0;
                o[am][bn][2] *= a1; o[am][bn][3] *= a1;
            }
        }

        // ---- P fragments (hi/lo) straight from S accumulators
        uint32_t pf[2][4][4], pg[2][4][4];
#pragma unroll
        for (int am = 0; am < 2; am++)
#pragma unroll
            for (int kk = 0; kk < 4; kk++) {
                split_pair(s[am][2*kk][0],   s[am][2*kk][1],   pf[am][kk][0], pg[am][kk][0]);
                split_pair(s[am][2*kk][2],   s[am][2*kk][3],   pf[am][kk][1], pg[am][kk][1]);
                split_pair(s[am][2*kk+1][0], s[am][2*kk+1][1], pf[am][kk][2], pg[am][kk][2]);
                split_pair(s[am][2*kk+1][2], s[am][2*kk+1][3], pf[am][kk][3], pg[am][kk][3]);
            }

        // ---- O += P V
#pragma unroll
        for (int kk = 0; kk < 4; kk++) {
            uint32_t vh[8][2], vl[8][2];
#pragma unroll
            for (int g = 0; g < 4; g++) {
                uint32_t a = voff + kk * (16 * KVP * 2) + g * 32;
                uint32_t r[4];
                LDSM4T(r, vh_b + a);
                vh[2*g][0] = r[0]; vh[2*g][1] = r[1];
                vh[2*g+1][0] = r[2]; vh[2*g+1][1] = r[3];
                LDSM4T(r, vl_b + a);
                vl[2*g][0] = r[0]; vl[2*g][1] = r[1];
                vl[2*g+1][0] = r[2]; vl[2*g+1][1] = r[3];
            }
#pragma unroll
            for (int bn = 0; bn < 8; bn++)
#pragma unroll
                for (int am = 0; am < 2; am++)
                    mma_bf16(o[am][bn], pg[am][kk], vh[bn]);
#pragma unroll
            for (int bn = 0; bn < 8; bn++)
#pragma unroll
                for (int am = 0; am < 2; am++)
                    mma_bf16(o[am][bn], pf[am][kk], vl[bn]);
#pragma unroll
            for (int bn = 0; bn < 8; bn++)
#pragma unroll
                for (int am = 0; am < 2; am++)
                    mma_bf16(o[am][bn], pf[am][kk], vh[bn]);
        }
    }

    // ---- epilogue: normalize, split, store ctx hi/lo
#pragma unroll
    for (int am = 0; am < 2; am++) {
        float inv0 = 1.f / lrow[am][0];
        float inv1 = 1.f / lrow[am][1];
        long r0 = rowb + i0 + wid * 32 + am * 16 + gid;
#pragma unroll
        for (int bn = 0; bn < 8; bn++) {
            int col = h * DH + bn * 8 + 2 * tig;
            uint32_t hh, ll;
            split_pair(o[am][bn][0] * inv0, o[am][bn][1] * inv0, hh, ll);
            *(uint32_t*)(ctxh + r0 * DIM + col) = hh;
            *(uint32_t*)(ctxl + r0 * DIM + col) = ll;
            split_pair(o[am][bn][2] * inv1, o[am][bn][3] * inv1, hh, ll);
            *(uint32_t*)(ctxh + (r0 + 8) * DIM + col) = hh;
            *(uint32_t*)(ctxl + (r0 + 8) * DIM + col) = ll;
        }
    }
}

// ---------------------------------------------------------------------------
extern "C" void kernel_launch(void* const* d_in, const int* in_sizes, int n_in,
                              void* d_out, int out_size)
{
    (void)in_sizes; (void)n_in; (void)out_size;
    const float* x    = (const float*)d_in[0];
    const float* Wqkv = (const float*)d_in[1];
    const float* Wout = (const float*)d_in[2];
    float* out = (float*)d_out;

    __nv_bfloat16 *xh, *xl, *wqh, *wql, *woh, *wol, *qh, *ql, *ch, *cl;
    cudaGetSymbolAddress((void**)&xh,  g_xh);
    cudaGetSymbolAddress((void**)&xl,  g_xl);
    cudaGetSymbolAddress((void**)&wqh, g_wqh);
    cudaGetSymbolAddress((void**)&wql, g_wql);
    cudaGetSymbolAddress((void**)&woh, g_woh);
    cudaGetSymbolAddress((void**)&wol, g_wol);
    cudaGetSymbolAddress((void**)&qh,  g_qh);
    cudaGetSymbolAddress((void**)&ql,  g_ql);
    cudaGetSymbolAddress((void**)&ch,  g_ch);
    cudaGetSymbolAddress((void**)&cl,  g_cl);

    cudaFuncSetAttribute(gemm_mma<0>,
                         cudaFuncAttributeMaxDynamicSharedMemorySize, GEMM_SMEM);
    cudaFuncSetAttribute(gemm_mma<1>,
                         cudaFuncAttributeMaxDynamicSharedMemorySize, GEMM_SMEM);

    // prep
    split_x_kernel<<<(MTOT * KD) / 1024, 256>>>(x, xh, xl);
    tsplit_kernel<<<dim3(E3 / 32, KD / 32), dim3(32, 8)>>>(Wqkv, wqh, wql, E3, KD);
    tsplit_kernel<<<dim3(DIM / 32, KD / 32), dim3(32, 8)>>>(Wout, woh, wol, DIM, KD);

    // 1) QKV projection -> split qkv (Q columns pre-scaled)
    gemm_mma<1><<<dim3(E3 / 256, MTOT / 128), 256, GEMM_SMEM>>>(
        xh, xl, wqh, wql, nullptr, qh, ql, MTOT, E3, KD, DIM);

    // 2) sliding-window attention -> split ctx
    attn_mma<<<dim3(SEQ / 128, NH, BATCH), 128>>>(qh, ql, ch, cl);

    // 3) output projection -> fp32 out
    gemm_mma<0><<<dim3(DIM / 256, MTOT / 128), 256, GEMM_SMEM>>>(
        ch, cl, woh, wol, out, nullptr, nullptr, MTOT, DIM, KD, 0);
}

// round 7
// speedup vs baseline: 1.0273x; 1.0272x over previous
#include <cuda_runtime.h>
#include <cuda_bf16.h>
#include <math.h>
#include <float.h>
#include <stdint.h>

#define BATCH 2
#define SEQ   2048
#define DIM   1024
#define NH    16
#define DH    64
#define WIN   512
#define E3    3072
#define MTOT  (BATCH * SEQ)   // 4096
#define KD    1024

// ---------------- scratch (device globals; no allocation) ------------------
__device__ __nv_bfloat16 g_xh[MTOT * KD],  g_xl[MTOT * KD];   // split x
__device__ __nv_bfloat16 g_wqh[E3 * KD],   g_wql[E3 * KD];    // Wqkv^T split
__device__ __nv_bfloat16 g_woh[DIM * KD],  g_wol[DIM * KD];   // Wout^T split
__device__ __nv_bfloat16 g_qh[MTOT * E3],  g_ql[MTOT * E3];   // split qkv
__device__ __nv_bfloat16 g_ch[MTOT * KD],  g_cl[MTOT * KD];   // split ctx

// ---------------- helpers ---------------------------------------------------
__device__ __forceinline__ uint32_t pack_bf16(float lo, float hi) {
    uint32_t r;
    asm("cvt.rn.bf16x2.f32 %0, %1, %2;" : "=r"(r) : "f"(hi), "f"(lo));
    return r;
}
__device__ __forceinline__ void split_pair(float x, float y, uint32_t& hi, uint32_t& lo) {
    hi = pack_bf16(x, y);
    float xh = __uint_as_float(hi << 16);
    float yh = __uint_as_float(hi & 0xFFFF0000u);
    lo = pack_bf16(x - xh, y - yh);
}
__device__ __forceinline__ void mma_bf16(float* c, const uint32_t* a, const uint32_t* b) {
    asm volatile(
        "mma.sync.aligned.m16n8k16.row.col.f32.bf16.bf16.f32 "
        "{%0,%1,%2,%3}, {%4,%5,%6,%7}, {%8,%9}, {%0,%1,%2,%3};"
        : "+f"(c[0]), "+f"(c[1]), "+f"(c[2]), "+f"(c[3])
        : "r"(a[0]), "r"(a[1]), "r"(a[2]), "r"(a[3]), "r"(b[0]), "r"(b[1]));
}
__device__ __forceinline__ uint32_t smem_u32(const void* p) {
    return (uint32_t)__cvta_generic_to_shared(p);
}
#define CP16(s, g) \
    asm volatile("cp.async.cg.shared.global [%0], [%1], 16;" :: "r"(s), "l"(g))
#define CP_COMMIT() asm volatile("cp.async.commit_group;")
#define CP_WAIT(n)  asm volatile("cp.async.wait_group %0;" :: "n"(n))
#define LDSM4(r, a) \
    asm volatile("ldmatrix.sync.aligned.m8n8.x4.shared.b16 {%0,%1,%2,%3}, [%4];" \
        : "=r"((r)[0]), "=r"((r)[1]), "=r"((r)[2]), "=r"((r)[3]) : "r"(a))
#define LDSM4T(r, a) \
    asm volatile("ldmatrix.sync.aligned.m8n8.x4.trans.shared.b16 {%0,%1,%2,%3}, [%4];" \
        : "=r"((r)[0]), "=r"((r)[1]), "=r"((r)[2]), "=r"((r)[3]) : "r"(a))

// ---------------------------------------------------------------------------
// Prep kernels
// ---------------------------------------------------------------------------
__global__ __launch_bounds__(256) void split_x_kernel(
    const float* __restrict__ x, __nv_bfloat16* __restrict__ xh,
    __nv_bfloat16* __restrict__ xl)
{
    int i = blockIdx.x * 256 + threadIdx.x;
    float4 v = ((const float4*)x)[i];
    uint32_t h0, l0, h1, l1;
    split_pair(v.x, v.y, h0, l0);
    split_pair(v.z, v.w, h1, l1);
    ((uint2*)xh)[i] = make_uint2(h0, h1);
    ((uint2*)xl)[i] = make_uint2(l0, l1);
}

// W[K][N] fp32 -> Wt hi/lo [N][K] bf16
__global__ __launch_bounds__(256) void tsplit_kernel(
    const float* __restrict__ W, __nv_bfloat16* __restrict__ Wth,
    __nv_bfloat16* __restrict__ Wtl, int N, int K)
{
    __shared__ float tile[32][33];
    int tx = threadIdx.x, ty = threadIdx.y;
    int n0 = blockIdx.x * 32, k0 = blockIdx.y * 32;
#pragma unroll
    for (int i = 0; i < 4; i++)
        tile[ty + 8 * i][tx] = W[(long)(k0 + ty + 8 * i) * N + n0 + tx];
    __syncthreads();
#pragma unroll
    for (int i = 0; i < 4; i++) {
        int n = ty + 8 * i;
        float v = tile[tx][n];
        __nv_bfloat16 h = __float2bfloat16(v);
        Wth[(long)(n0 + n) * K + k0 + tx] = h;
        Wtl[(long)(n0 + n) * K + k0 + tx] = __float2bfloat16(v - __bfloat162float(h));
    }
}

// ---------------------------------------------------------------------------
// bf16x3 GEMM on mma.sync. C = Al*Bh + Ah*Bl + Ah*Bh.
// A: [M][K] bf16 K-major (pre-split). B: [N][K] bf16 K-major (pre-split).
// Block tile 128x128, BK=32, 256 thr = 8 warps (2m x 4n of 64x32 warp tiles).
// 2 CTAs/SM (__launch_bounds__(256,2)); cp.async double buffer; ldmatrix.
// MODE 0: fp32 C.  MODE 1: split bf16 hi/lo C (cols < qcols scaled by 0.125).
// ---------------------------------------------------------------------------
#define LDT      40                           // bf16 per smem row (32 + 8 pad)
#define A_BYTES  (128 * LDT * 2)              // 10240
#define B_BYTES  (128 * LDT * 2)              // 10240
#define STG      (2 * A_BYTES + 2 * B_BYTES)  // 40960
#define GEMM_SMEM (2 * STG)                   // 81920

template <int MODE>
__global__ __launch_bounds__(256, 2) void gemm_mma(
    const __nv_bfloat16* __restrict__ Ah, const __nv_bfloat16* __restrict__ Al,
    const __nv_bfloat16* __restrict__ Bh, const __nv_bfloat16* __restrict__ Bl,
    float* __restrict__ Cf, __nv_bfloat16* __restrict__ Ch,
    __nv_bfloat16* __restrict__ Cl, int M, int N, int K, int qcols)
{
    extern __shared__ char smem[];
    const uint32_t sb = smem_u32(smem);
    const int tid = threadIdx.x, wid = tid >> 5, lane = tid & 31;
    const int wm = (wid & 1) * 64, wn = (wid >> 1) * 32;
    const long arow0 = (long)blockIdx.y * 128;
    const long brow0 = (long)blockIdx.x * 128;

    float acc[4][4][4] = {};

    // fragment base offsets within a stage
    const uint32_t a_off =
        (uint32_t)((wm + (lane & 7) + ((lane & 8) ? 8 : 0)) * (LDT * 2)
                   + ((lane & 16) ? 16 : 0));
    const uint32_t b_off = (uint32_t)(2 * A_BYTES
                   + (wn + (lane & 7) + ((lane & 16) ? 8 : 0)) * (LDT * 2)
                   + ((lane & 8) ? 16 : 0));

    const int nT = K / 32;

    auto issue = [&](int t) {
        const int s = t & 1, k0 = t * 32;
        const uint32_t st = sb + s * STG;
        // A hi/lo: 512 chunks each (128 rows x 4 chunks)
#pragma unroll
        for (int i = 0; i < 2; i++) {
            int idx = i * 256 + tid;
            int row = idx >> 2, kc = idx & 3;
            uint32_t so = st + row * (LDT * 2) + kc * 16;
            long go = (arow0 + row) * K + k0 + kc * 8;
            CP16(so, Ah + go);
            CP16(so + A_BYTES, Al + go);
        }
        // B hi/lo: 512 chunks each
#pragma unroll
        for (int i = 0; i < 2; i++) {
            int idx = i * 256 + tid;
            int row = idx >> 2, kc = idx & 3;
            uint32_t so = st + 2 * A_BYTES + row * (LDT * 2) + kc * 16;
            long go = (brow0 + row) * K + k0 + kc * 8;
            CP16(so, Bh + go);
            CP16(so + B_BYTES, Bl + go);
        }
        CP_COMMIT();
    };

    issue(0);
    for (int t = 0; t < nT; t++) {
        if (t + 1 < nT) { issue(t + 1); CP_WAIT(1); }
        else            { CP_WAIT(0); }
        __syncthreads();

        const uint32_t st = sb + (t & 1) * STG;
#pragma unroll
        for (int ks = 0; ks < 2; ks++) {
            uint32_t ah[4][4], al[4][4], bh[4][2], bl[4][2];
#pragma unroll
            for (int am = 0; am < 4; am++) {
                uint32_t a = st + a_off + am * (16 * LDT * 2) + ks * 32;
                LDSM4(ah[am], a);
                LDSM4(al[am], a + A_BYTES);
            }
#pragma unroll
            for (int g = 0; g < 2; g++) {
                uint32_t a = st + b_off + g * (16 * LDT * 2) + ks * 32;
                uint32_t r[4];
                LDSM4(r, a);
                bh[2*g][0] = r[0]; bh[2*g][1] = r[1];
                bh[2*g+1][0] = r[2]; bh[2*g+1][1] = r[3];
                LDSM4(r, a + B_BYTES);
                bl[2*g][0] = r[0]; bl[2*g][1] = r[1];
                bl[2*g+1][0] = r[2]; bl[2*g+1][1] = r[3];
            }
#pragma unroll
            for (int am = 0; am < 4; am++)
#pragma unroll
                for (int bn = 0; bn < 4; bn++)
                    mma_bf16(acc[am][bn], al[am], bh[bn]);
#pragma unroll
            for (int am = 0; am < 4; am++)
#pragma unroll
                for (int bn = 0; bn < 4; bn++)
                    mma_bf16(acc[am][bn], ah[am], bl[bn]);
#pragma unroll
            for (int am = 0; am < 4; am++)
#pragma unroll
                for (int bn = 0; bn < 4; bn++)
                    mma_bf16(acc[am][bn], ah[am], bh[bn]);
        }
        __syncthreads();
    }

    // epilogue
#pragma unroll
    for (int am = 0; am < 4; am++)
#pragma unroll
        for (int bn = 0; bn < 4; bn++) {
            int row = blockIdx.y * 128 + wm + am * 16 + (lane >> 2);
            int col = blockIdx.x * 128 + wn + bn * 8 + 2 * (lane & 3);
            if (MODE == 0) {
                *(float2*)(Cf + (long)row * N + col) =
                    make_float2(acc[am][bn][0], acc[am][bn][1]);
                *(float2*)(Cf + (long)(row + 8) * N + col) =
                    make_float2(acc[am][bn][2], acc[am][bn][3]);
            } else {
                float scl = (col < qcols) ? 0.125f : 1.0f;
                uint32_t hh, ll;
                split_pair(acc[am][bn][0] * scl, acc[am][bn][1] * scl, hh, ll);
                *(uint32_t*)(Ch + (long)row * N + col) = hh;
                *(uint32_t*)(Cl + (long)row * N + col) = ll;
                split_pair(acc[am][bn][2] * scl, acc[am][bn][3] * scl, hh, ll);
                *(uint32_t*)(Ch + (long)(row + 8) * N + col) = hh;
                *(uint32_t*)(Cl + (long)(row + 8) * N + col) = ll;
            }
        }
}

// ---------------------------------------------------------------------------
// Sliding-window flash attention, bf16 hi/lo 3-pass on mma.sync.
// Inputs pre-split (Q pre-scaled). 128 q-rows/block, 4 warps, key tile 64.
// ---------------------------------------------------------------------------
#define KVP 72   // bf16 per smem row (64 + 8 pad); 144B rows, 16B aligned

__global__ __launch_bounds__(128) void attn_mma(
    const __nv_bfloat16* __restrict__ qh, const __nv_bfloat16* __restrict__ ql,
    __nv_bfloat16* __restrict__ ctxh, __nv_bfloat16* __restrict__ ctxl)
{
    __shared__ __nv_bfloat16 Kh[64 * KVP], Kl[64 * KVP];
    __shared__ __nv_bfloat16 Vh[64 * KVP], Vl[64 * KVP];

    const int tid  = threadIdx.x;
    const int wid  = tid >> 5;
    const int lane = tid & 31;
    const int gid  = lane >> 2;
    const int tig  = lane & 3;
    const int i0   = blockIdx.x * 128;
    const int h    = blockIdx.y;
    const int b    = blockIdx.z;

    const long rowb = (long)b * SEQ;
    const int qcol = h * DH;
    const int kcol = DIM + h * DH;
    const int vcol = 2 * DIM + h * DH;

    // Q fragments (already scaled + split by GEMM1 epilogue)
    uint32_t qfh[2][4][4], qfl[2][4][4];
#pragma unroll
    for (int am = 0; am < 2; am++) {
        long r = rowb + i0 + wid * 32 + am * 16 + gid;
#pragma unroll
        for (int s = 0; s < 4; s++) {
            int c = qcol + s * 16 + 2 * tig;
            qfh[am][s][0] = *(const uint32_t*)(qh + r * E3 + c);
            qfh[am][s][1] = *(const uint32_t*)(qh + (r + 8) * E3 + c);
            qfh[am][s][2] = *(const uint32_t*)(qh + r * E3 + c + 8);
            qfh[am][s][3] = *(const uint32_t*)(qh + (r + 8) * E3 + c + 8);
            qfl[am][s][0] = *(const uint32_t*)(ql + r * E3 + c);
            qfl[am][s][1] = *(const uint32_t*)(ql + (r + 8) * E3 + c);
            qfl[am][s][2] = *(const uint32_t*)(ql + r * E3 + c + 8);
            qfl[am][s][3] = *(const uint32_t*)(ql + (r + 8) * E3 + c + 8);
        }
    }

    const uint32_t kh_b = smem_u32(Kh), kl_b = smem_u32(Kl);
    const uint32_t vh_b = smem_u32(Vh), vl_b = smem_u32(Vl);
    const uint32_t koff = (uint32_t)(((lane & 7) + ((lane & 16) ? 8 : 0)) * (KVP * 2)
                                     + ((lane & 8) ? 16 : 0));
    const uint32_t voff = (uint32_t)(((lane & 7) + ((lane & 8) ? 8 : 0)) * (KVP * 2)
                                     + ((lane & 16) ? 16 : 0));

    float mrow[2][2], lrow[2][2], o[2][8][4] = {};
#pragma unroll
    for (int am = 0; am < 2; am++) {
        mrow[am][0] = -FLT_MAX; mrow[am][1] = -FLT_MAX;
        lrow[am][0] = 0.f;      lrow[am][1] = 0.f;
    }

    int t0 = (i0 - WIN + 1) >> 6; if (t0 < 0) t0 = 0;
    const int t1 = (i0 + 127) >> 6;

    for (int t = t0; t <= t1; t++) {
        const int kt0 = t << 6;
        __syncthreads();

#pragma unroll
        for (int i = 0; i < 4; i++) {
            int idx = i * 128 + tid;
            int row = idx >> 3, ch = idx & 7;
            long gro = (rowb + kt0 + row) * E3;
            uint32_t so = row * (KVP * 2) + ch * 16;
            CP16(kh_b + so, qh + gro + kcol + ch * 8);
            CP16(kl_b + so, ql + gro + kcol + ch * 8);
            CP16(vh_b + so, qh + gro + vcol + ch * 8);
            CP16(vl_b + so, ql + gro + vcol + ch * 8);
        }
        CP_COMMIT();
        CP_WAIT(0);
        __syncthreads();

        // ---- S = Q K^T
        float s[2][8][4] = {};
#pragma unroll
        for (int ks = 0; ks < 4; ks++) {
            uint32_t kh[8][2], kl[8][2];
#pragma unroll
            for (int g = 0; g < 4; g++) {
                uint32_t a = koff + g * (16 * KVP * 2) + ks * 32;
                uint32_t r[4];
                LDSM4(r, kh_b + a);
                kh[2*g][0] = r[0]; kh[2*g][1] = r[1];
                kh[2*g+1][0] = r[2]; kh[2*g+1][1] = r[3];
                LDSM4(r, kl_b + a);
                kl[2*g][0] = r[0]; kl[2*g][1] = r[1];
                kl[2*g+1][0] = r[2]; kl[2*g+1][1] = r[3];
            }
#pragma unroll
            for (int bn = 0; bn < 8; bn++)
#pragma unroll
                for (int am = 0; am < 2; am++)
                    mma_bf16(s[am][bn], qfl[am][ks], kh[bn]);
#pragma unroll
            for (int bn = 0; bn < 8; bn++)
#pragma unroll
                for (int am = 0; am < 2; am++)
                    mma_bf16(s[am][bn], qfh[am][ks], kl[bn]);
#pragma unroll
            for (int bn = 0; bn < 8; bn++)
#pragma unroll
                for (int am = 0; am < 2; am++)
                    mma_bf16(s[am][bn], qfh[am][ks], kh[bn]);
        }

        // ---- mask + online softmax
#pragma unroll
        for (int am = 0; am < 2; am++) {
            int qi0 = i0 + wid * 32 + am * 16 + gid;
            int qi1 = qi0 + 8;
#pragma unroll
            for (int bn = 0; bn < 8; bn++) {
                int c0 = kt0 + bn * 8 + 2 * tig, c1 = c0 + 1;
                if (c0 > qi0 || c0 < qi0 - (WIN - 1)) s[am][bn][0] = -FLT_MAX;
                if (c1 > qi0 || c1 < qi0 - (WIN - 1)) s[am][bn][1] = -FLT_MAX;
                if (c0 > qi1 || c0 < qi1 - (WIN - 1)) s[am][bn][2] = -FLT_MAX;
                if (c1 > qi1 || c1 < qi1 - (WIN - 1)) s[am][bn][3] = -FLT_MAX;
            }
            float mx0 = -FLT_MAX, mx1 = -FLT_MAX;
#pragma unroll
            for (int bn = 0; bn < 8; bn++) {
                mx0 = fmaxf(mx0, fmaxf(s[am][bn][0], s[am][bn][1]));
                mx1 = fmaxf(mx1, fmaxf(s[am][bn][2], s[am][bn][3]));
            }
            mx0 = fmaxf(mx0, __shfl_xor_sync(0xffffffffu, mx0, 1));
            mx0 = fmaxf(mx0, __shfl_xor_sync(0xffffffffu, mx0, 2));
            mx1 = fmaxf(mx1, __shfl_xor_sync(0xffffffffu, mx1, 1));
            mx1 = fmaxf(mx1, __shfl_xor_sync(0xffffffffu, mx1, 2));
            float mn0 = fmaxf(mrow[am][0], mx0);
            float mn1 = fmaxf(mrow[am][1], mx1);
            float a0 = __expf(mrow[am][0] - mn0);
            float a1 = __expf(mrow[am][1] - mn1);
            mrow[am][0] = mn0; mrow[am][1] = mn1;
            float rs0 = 0.f, rs1 = 0.f;
#pragma unroll
            for (int bn = 0; bn < 8; bn++) {
                s[am][bn][0] = __expf(s[am][bn][0] - mn0);
                s[am][bn][1] = __expf(s[am][bn][1] - mn0);
                s[am][bn][2] = __expf(s[am][bn][2] - mn1);
                s[am][bn][3] = __expf(s[am][bn][3] - mn1);
                rs0 += s[am][bn][0] + s[am][bn][1];
                rs1 += s[am][bn][2] + s[am][bn][3];
            }
            rs0 += __shfl_xor_sync(0xffffffffu, rs0, 1);
            rs0 += __shfl_xor_sync(0xffffffffu, rs0, 2);
            rs1 += __shfl_xor_sync(0xffffffffu, rs1, 1);
            rs1 += __shfl_xor_sync(0xffffffffu, rs1, 2);
            lrow[am][0] = lrow[am][0] * a0 + rs0;
            lrow[am][1] = lrow[am][1] * a1 + rs1;
#pragma unroll
            for (int bn = 0; bn < 8; bn++) {
                o[am][bn][0] *= a0; o[am][bn][1] *= a0;
                o[am][bn][2] *= a1; o[am][bn][3] *= a1;
            }
        }

        // ---- P fragments (hi/lo) straight from S accumulators
        uint32_t pf[2][4][4], pg[2][4][4];
#pragma unroll
        for (int am = 0; am < 2; am++)
#pragma unroll
            for (int kk = 0; kk < 4; kk++) {
                split_pair(s[am][2*kk][0],   s[am][2*kk][1],   pf[am][kk][0], pg[am][kk][0]);
                split_pair(s[am][2*kk][2],   s[am][2*kk][3],   pf[am][kk][1], pg[am][kk][1]);
                split_pair(s[am][2*kk+1][0], s[am][2*kk+1][1], pf[am][kk][2], pg[am][kk][2]);
                split_pair(s[am][2*kk+1][2], s[am][2*kk+1][3], pf[am][kk][3], pg[am][kk][3]);
            }

        // ---- O += P V
#pragma unroll
        for (int kk = 0; kk < 4; kk++) {
            uint32_t vh[8][2], vl[8][2];
#pragma unroll
            for (int g = 0; g < 4; g++) {
                uint32_t a = voff + kk * (16 * KVP * 2) + g * 32;
                uint32_t r[4];
                LDSM4T(r, vh_b + a);
                vh[2*g][0] = r[0]; vh[2*g][1] = r[1];
                vh[2*g+1][0] = r[2]; vh[2*g+1][1] = r[3];
                LDSM4T(r, vl_b + a);
                vl[2*g][0] = r[0]; vl[2*g][1] = r[1];
                vl[2*g+1][0] = r[2]; vl[2*g+1][1] = r[3];
            }
#pragma unroll
            for (int bn = 0; bn < 8; bn++)
#pragma unroll
                for (int am = 0; am < 2; am++)
                    mma_bf16(o[am][bn], pg[am][kk], vh[bn]);
#pragma unroll
            for (int bn = 0; bn < 8; bn++)
#pragma unroll
                for (int am = 0; am < 2; am++)
                    mma_bf16(o[am][bn], pf[am][kk], vl[bn]);
#pragma unroll
            for (int bn = 0; bn < 8; bn++)
#pragma unroll
                for (int am = 0; am < 2; am++)
                    mma_bf16(o[am][bn], pf[am][kk], vh[bn]);
        }
    }

    // ---- epilogue: normalize, split, store ctx hi/lo
#pragma unroll
    for (int am = 0; am < 2; am++) {
        float inv0 = 1.f / lrow[am][0];
        float inv1 = 1.f / lrow[am][1];
        long r0 = rowb + i0 + wid * 32 + am * 16 + gid;
#pragma unroll
        for (int bn = 0; bn < 8; bn++) {
            int col = h * DH + bn * 8 + 2 * tig;
            uint32_t hh, ll;
            split_pair(o[am][bn][0] * inv0, o[am][bn][1] * inv0, hh, ll);
            *(uint32_t*)(ctxh + r0 * DIM + col) = hh;
            *(uint32_t*)(ctxl + r0 * DIM + col) = ll;
            split_pair(o[am][bn][2] * inv1, o[am][bn][3] * inv1, hh, ll);
            *(uint32_t*)(ctxh + (r0 + 8) * DIM + col) = hh;
            *(uint32_t*)(ctxl + (r0 + 8) * DIM + col) = ll;
        }
    }
}

// ---------------------------------------------------------------------------
extern "C" void kernel_launch(void* const* d_in, const int* in_sizes, int n_in,
                              void* d_out, int out_size)
{
    (void)in_sizes; (void)n_in; (void)out_size;
    const float* x    = (const float*)d_in[0];
    const float* Wqkv = (const float*)d_in[1];
    const float* Wout = (const float*)d_in[2];
    float* out = (float*)d_out;

    __nv_bfloat16 *xh, *xl, *wqh, *wql, *woh, *wol, *qh, *ql, *ch, *cl;
    cudaGetSymbolAddress((void**)&xh,  g_xh);
    cudaGetSymbolAddress((void**)&xl,  g_xl);
    cudaGetSymbolAddress((void**)&wqh, g_wqh);
    cudaGetSymbolAddress((void**)&wql, g_wql);
    cudaGetSymbolAddress((void**)&woh, g_woh);
    cudaGetSymbolAddress((void**)&wol, g_wol);
    cudaGetSymbolAddress((void**)&qh,  g_qh);
    cudaGetSymbolAddress((void**)&ql,  g_ql);
    cudaGetSymbolAddress((void**)&ch,  g_ch);
    cudaGetSymbolAddress((void**)&cl,  g_cl);

    cudaFuncSetAttribute(gemm_mma<0>,
                         cudaFuncAttributeMaxDynamicSharedMemorySize, GEMM_SMEM);
    cudaFuncSetAttribute(gemm_mma<1>,
                         cudaFuncAttributeMaxDynamicSharedMemorySize, GEMM_SMEM);

    // prep
    split_x_kernel<<<(MTOT * KD) / 1024, 256>>>(x, xh, xl);
    tsplit_kernel<<<dim3(E3 / 32, KD / 32), dim3(32, 8)>>>(Wqkv, wqh, wql, E3, KD);
    tsplit_kernel<<<dim3(DIM / 32, KD / 32), dim3(32, 8)>>>(Wout, woh, wol, DIM, KD);

    // 1) QKV projection -> split qkv (Q columns pre-scaled)
    gemm_mma<1><<<dim3(E3 / 128, MTOT / 128), 256, GEMM_SMEM>>>(
        xh, xl, wqh, wql, nullptr, qh, ql, MTOT, E3, KD, DIM);

    // 2) sliding-window attention -> split ctx
    attn_mma<<<dim3(SEQ / 128, NH, BATCH), 128>>>(qh, ql, ch, cl);

    // 3) output projection -> fp32 out
    gemm_mma<0><<<dim3(DIM / 128, MTOT / 128), 256, GEMM_SMEM>>>(
        ch, cl, woh, wol, out, nullptr, nullptr, MTOT, DIM, KD, 0);
}